// round 1
// baseline (speedup 1.0000x reference)
#include <cuda_runtime.h>

#define NN   100000
#define EE   256000
#define EMB  300
#define EMB2 600
#define LAY  5
#define C75  (EMB / 4)   // 75 float4 chunks per node row

// ---------------- scratch (static device arrays; no allocation) ----------------
__device__ __align__(128) float g_agg [(size_t)NN * EMB];   // (1+eps)*h + segment_sum(msg)
__device__ __align__(128) float g_z1  [(size_t)NN * EMB2];  // GEMM1 output
__device__ __align__(128) float g_z2  [(size_t)NN * EMB];   // GEMM2 output
__device__ __align__(128) float g_h   [(size_t)NN * EMB];   // layer output (ping buffer)
__device__ __align__(128) float g_comb[18 * EMB];           // all (ea0,ea1) edge embeddings
__device__ __align__(128) float g_stats[1800];              // [0:600) sum1 [600:1200) sq1 [1200:1500) sum2 [1500:1800) sq2
__device__ __align__(128) float g_scale1[EMB2];
__device__ __align__(128) float g_shift1[EMB2];
__device__ __align__(128) float g_scale2[EMB];
__device__ __align__(128) float g_shift2[EMB];

// ---------------- f32x2 packed-FMA helpers ----------------
__device__ __forceinline__ unsigned long long dup_f32(float a) {
    unsigned long long d;
    asm("mov.b64 %0, {%1, %1};" : "=l"(d) : "r"(__float_as_uint(a)));
    return d;
}
__device__ __forceinline__ void ffma2(unsigned long long& c, unsigned long long a, unsigned long long b) {
    asm("fma.rn.f32x2 %0, %1, %2, %0;" : "+l"(c) : "l"(a), "l"(b));
}
__device__ __forceinline__ float2 unpack2(unsigned long long v) {
    unsigned int lo, hi;
    asm("mov.b64 {%0, %1}, %2;" : "=r"(lo), "=r"(hi) : "l"(v));
    return make_float2(__uint_as_float(lo), __uint_as_float(hi));
}

// ---------------- small kernels ----------------
__global__ void build_comb(const float* __restrict__ Wb, int l) {
    int t = blockIdx.x * 256 + threadIdx.x;
    if (t < 18 * EMB) {
        int p = t / EMB;
        int f = t - p * EMB;
        int a = p / 3, b = p - a * 3;
        const float* w = Wb + (size_t)l * EMB * 9 + (size_t)f * 9;
        g_comb[p * EMB + f] = w[a] + w[6 + b];
    }
}

__global__ void zero_stats() {
    int t = blockIdx.x * 256 + threadIdx.x;
    if (t < 1800) g_stats[t] = 0.0f;
}

__global__ void init_agg(const float* __restrict__ x, int use_x, const float* __restrict__ eps, int l) {
    int i = blockIdx.x * 256 + threadIdx.x;
    if (i < NN * C75) {
        const float4* h = reinterpret_cast<const float4*>(use_x ? x : g_h);
        float s = 1.0f + eps[l];
        float4 v = h[i];
        v.x *= s; v.y *= s; v.z *= s; v.w *= s;
        reinterpret_cast<float4*>(g_agg)[i] = v;
    }
}

__global__ void edge_scatter(const float* __restrict__ x, int use_x,
                             const int* __restrict__ ei, const int* __restrict__ attr) {
    int idx = blockIdx.x * 256 + threadIdx.x;
    if (idx >= EE * C75) return;
    int e = idx / C75;
    int c = idx - e * C75;
    const float* h = use_x ? x : g_h;
    int src = ei[e];
    int dst = ei[EE + e];
    int2 av = *reinterpret_cast<const int2*>(attr + 2 * e);
    float4 hv = *reinterpret_cast<const float4*>(h + (size_t)src * EMB + 4 * c);
    float4 ev = *reinterpret_cast<const float4*>(g_comb + (av.x * 3 + av.y) * EMB + 4 * c);
    float4 m;
    m.x = fmaxf(hv.x + ev.x, 0.0f);
    m.y = fmaxf(hv.y + ev.y, 0.0f);
    m.z = fmaxf(hv.z + ev.z, 0.0f);
    m.w = fmaxf(hv.w + ev.w, 0.0f);
    float* a = g_agg + (size_t)dst * EMB + 4 * c;
    atomicAdd(a + 0, m.x);
    atomicAdd(a + 1, m.y);
    atomicAdd(a + 2, m.z);
    atomicAdd(a + 3, m.w);
}

// ---------------- fused GEMM (+A-transform, +bias, +BN-stat reduction) ----------------
// C[M,Nc] = act(A') @ W^T + bias,  W row-major [Nc,K]
// sel==0: A = g_agg, C = g_z1, no transform, stats -> [0,600)
// sel==1: A = relu(bn1(g_z1)) on-the-fly, C = g_z2, stats -> [1200,1500)
__global__ __launch_bounds__(256, 2)
void gemm_bn(int sel, const float* __restrict__ W, const float* __restrict__ bias,
             int M, int Nc, int K) {
    const float* A;
    float* C;
    const float* ascale;
    const float* ashift;
    float* statSum;
    float* statSq;
    int transformA;
    if (sel == 0) {
        A = g_agg; C = g_z1; ascale = nullptr; ashift = nullptr; transformA = 0;
        statSum = g_stats; statSq = g_stats + 600;
    } else {
        A = g_z1; C = g_z2; ascale = g_scale1; ashift = g_shift1; transformA = 1;
        statSum = g_stats + 1200; statSq = g_stats + 1500;
    }

    __shared__ float As[32][132];   // [k][m], padded
    __shared__ float Bs[32][68];    // [k][n], padded
    __shared__ float sSum[64], sSq[64];

    int tid  = threadIdx.x;
    int row0 = blockIdx.x * 128;
    int col0 = blockIdx.y * 64;
    int ty = tid >> 4, tx = tid & 15;

    unsigned long long acc[4][4];
#pragma unroll
    for (int i = 0; i < 4; i++)
#pragma unroll
        for (int j = 0; j < 4; j++) acc[i][j] = 0ull;

    int lr = tid >> 3;          // 0..31
    int lk = (tid & 7) * 4;     // 0..28

    for (int k0 = 0; k0 < K; k0 += 32) {
        // ---- load A tile (128 x 32), transposed into As[k][m] ----
#pragma unroll
        for (int p = 0; p < 4; p++) {
            int r = lr + p * 32;
            int grow = row0 + r;
            int gk = k0 + lk;
            float4 v = make_float4(0.f, 0.f, 0.f, 0.f);
            if (grow < M && gk < K) {
                v = *reinterpret_cast<const float4*>(A + (size_t)grow * K + gk);
                if (transformA) {
                    float4 s = *reinterpret_cast<const float4*>(ascale + gk);
                    float4 t = *reinterpret_cast<const float4*>(ashift + gk);
                    v.x = fmaxf(fmaf(v.x, s.x, t.x), 0.f);
                    v.y = fmaxf(fmaf(v.y, s.y, t.y), 0.f);
                    v.z = fmaxf(fmaf(v.z, s.z, t.z), 0.f);
                    v.w = fmaxf(fmaf(v.w, s.w, t.w), 0.f);
                }
            }
            As[lk + 0][r] = v.x;
            As[lk + 1][r] = v.y;
            As[lk + 2][r] = v.z;
            As[lk + 3][r] = v.w;
        }
        // ---- load B tile (64 x 32), transposed into Bs[k][n] ----
#pragma unroll
        for (int p = 0; p < 2; p++) {
            int r = lr + p * 32;
            int gcol = col0 + r;
            int gk = k0 + lk;
            float4 v = make_float4(0.f, 0.f, 0.f, 0.f);
            if (gcol < Nc && gk < K)
                v = *reinterpret_cast<const float4*>(W + (size_t)gcol * K + gk);
            Bs[lk + 0][r] = v.x;
            Bs[lk + 1][r] = v.y;
            Bs[lk + 2][r] = v.z;
            Bs[lk + 3][r] = v.w;
        }
        __syncthreads();
        // ---- compute: 8 rows (as 4 f32x2 pairs) x 4 cols per thread ----
#pragma unroll
        for (int kk = 0; kk < 32; kk++) {
            ulonglong2 a01 = *reinterpret_cast<const ulonglong2*>(&As[kk][ty * 8]);
            ulonglong2 a23 = *reinterpret_cast<const ulonglong2*>(&As[kk][ty * 8 + 4]);
            float4 b = *reinterpret_cast<const float4*>(&Bs[kk][tx * 4]);
            unsigned long long av[4] = {a01.x, a01.y, a23.x, a23.y};
            unsigned long long bd0 = dup_f32(b.x);
            unsigned long long bd1 = dup_f32(b.y);
            unsigned long long bd2 = dup_f32(b.z);
            unsigned long long bd3 = dup_f32(b.w);
#pragma unroll
            for (int i = 0; i < 4; i++) {
                ffma2(acc[i][0], av[i], bd0);
                ffma2(acc[i][1], av[i], bd1);
                ffma2(acc[i][2], av[i], bd2);
                ffma2(acc[i][3], av[i], bd3);
            }
        }
        __syncthreads();
    }

    // ---- epilogue: bias, store, per-column sum/sumsq for BN ----
    if (tid < 64) { sSum[tid] = 0.f; sSq[tid] = 0.f; }
    __syncthreads();

    int colg = col0 + tx * 4;
    bool colok = colg < Nc;   // Nc is a multiple of 4
    float4 bv = make_float4(0.f, 0.f, 0.f, 0.f);
    if (colok) bv = *reinterpret_cast<const float4*>(bias + colg);

    float cs0 = 0, cs1 = 0, cs2 = 0, cs3 = 0;
    float cq0 = 0, cq1 = 0, cq2 = 0, cq3 = 0;
#pragma unroll
    for (int i = 0; i < 4; i++) {
        float2 u0 = unpack2(acc[i][0]);
        float2 u1 = unpack2(acc[i][1]);
        float2 u2 = unpack2(acc[i][2]);
        float2 u3 = unpack2(acc[i][3]);
        int rowa = row0 + ty * 8 + 2 * i;
        if (colok && rowa < M) {
            float4 o = make_float4(u0.x + bv.x, u1.x + bv.y, u2.x + bv.z, u3.x + bv.w);
            *reinterpret_cast<float4*>(C + (size_t)rowa * Nc + colg) = o;
            cs0 += o.x; cs1 += o.y; cs2 += o.z; cs3 += o.w;
            cq0 += o.x * o.x; cq1 += o.y * o.y; cq2 += o.z * o.z; cq3 += o.w * o.w;
        }
        int rowb = rowa + 1;
        if (colok && rowb < M) {
            float4 o = make_float4(u0.y + bv.x, u1.y + bv.y, u2.y + bv.z, u3.y + bv.w);
            *reinterpret_cast<float4*>(C + (size_t)rowb * Nc + colg) = o;
            cs0 += o.x; cs1 += o.y; cs2 += o.z; cs3 += o.w;
            cq0 += o.x * o.x; cq1 += o.y * o.y; cq2 += o.z * o.z; cq3 += o.w * o.w;
        }
    }
    if (colok) {
        atomicAdd(&sSum[tx * 4 + 0], cs0);
        atomicAdd(&sSum[tx * 4 + 1], cs1);
        atomicAdd(&sSum[tx * 4 + 2], cs2);
        atomicAdd(&sSum[tx * 4 + 3], cs3);
        atomicAdd(&sSq[tx * 4 + 0], cq0);
        atomicAdd(&sSq[tx * 4 + 1], cq1);
        atomicAdd(&sSq[tx * 4 + 2], cq2);
        atomicAdd(&sSq[tx * 4 + 3], cq3);
    }
    __syncthreads();
    if (tid < 64 && col0 + tid < Nc) {
        atomicAdd(&statSum[col0 + tid], sSum[tid]);
        atomicAdd(&statSq [col0 + tid], sSq [tid]);
    }
}

__global__ void finalize_bn(const float* __restrict__ gamma, const float* __restrict__ beta,
                            int l, int sel) {
    int Ccols = sel ? EMB : EMB2;
    const float* sum = sel ? (g_stats + 1200) : g_stats;
    const float* sq  = sel ? (g_stats + 1500) : (g_stats + 600);
    float* scale = sel ? g_scale2 : g_scale1;
    float* shift = sel ? g_shift2 : g_shift1;
    int j = blockIdx.x * 256 + threadIdx.x;
    if (j < Ccols) {
        float inv = 1.0f / (float)NN;
        float m = sum[j] * inv;
        float v = sq[j] * inv - m * m;
        float sc = gamma[l * Ccols + j] * rsqrtf(v + 1e-5f);
        scale[j] = sc;
        shift[j] = beta[l * Ccols + j] - m * sc;
    }
}

__global__ void apply_out(float* __restrict__ dout, int use_dout, int do_relu) {
    int i = blockIdx.x * 256 + threadIdx.x;
    if (i < NN * C75) {
        int c4 = (i % C75) * 4;
        float4 v = reinterpret_cast<const float4*>(g_z2)[i];
        float4 sc = *reinterpret_cast<const float4*>(g_scale2 + c4);
        float4 sh = *reinterpret_cast<const float4*>(g_shift2 + c4);
        v.x = fmaf(v.x, sc.x, sh.x);
        v.y = fmaf(v.y, sc.y, sh.y);
        v.z = fmaf(v.z, sc.z, sh.z);
        v.w = fmaf(v.w, sc.w, sh.w);
        if (do_relu) {
            v.x = fmaxf(v.x, 0.f);
            v.y = fmaxf(v.y, 0.f);
            v.z = fmaxf(v.z, 0.f);
            v.w = fmaxf(v.w, 0.f);
        }
        float4* o = use_dout ? reinterpret_cast<float4*>(dout) : reinterpret_cast<float4*>(g_h);
        o[i] = v;
    }
}

// ---------------- host ----------------
extern "C" void kernel_launch(void* const* d_in, const int* in_sizes, int n_in,
                              void* d_out, int out_size) {
    const float* x    = (const float*)d_in[0];
    const float* Wb   = (const float*)d_in[1];
    const float* eps  = (const float*)d_in[2];
    const float* W1   = (const float*)d_in[3];
    const float* b1   = (const float*)d_in[4];
    const float* bn1g = (const float*)d_in[5];
    const float* bn1b = (const float*)d_in[6];
    const float* W2   = (const float*)d_in[7];
    const float* b2   = (const float*)d_in[8];
    const float* bng  = (const float*)d_in[9];
    const float* bnb  = (const float*)d_in[10];
    const int*   ei   = (const int*)d_in[11];
    const int*   attr = (const int*)d_in[12];
    float* out = (float*)d_out;

    const int gridA = (NN * C75 + 255) / 256;   // node-elementwise
    const int gridE = (EE * C75 + 255) / 256;   // edge-chunk
    const int gridM = (NN + 127) / 128;         // GEMM row tiles (782)

    for (int l = 0; l < LAY; l++) {
        int use_x = (l == 0) ? 1 : 0;
        build_comb<<<(18 * EMB + 255) / 256, 256>>>(Wb, l);
        zero_stats<<<(1800 + 255) / 256, 256>>>();
        init_agg<<<gridA, 256>>>(x, use_x, eps, l);
        edge_scatter<<<gridE, 256>>>(x, use_x, ei, attr);
        gemm_bn<<<dim3(gridM, (EMB2 + 63) / 64), 256>>>(
            0, W1 + (size_t)l * EMB2 * EMB, b1 + l * EMB2, NN, EMB2, EMB);
        finalize_bn<<<(EMB2 + 255) / 256, 256>>>(bn1g, bn1b, l, 0);
        gemm_bn<<<dim3(gridM, (EMB + 63) / 64), 256>>>(
            1, W2 + (size_t)l * EMB * EMB2, b2 + l * EMB, NN, EMB, EMB2);
        finalize_bn<<<(EMB + 255) / 256, 256>>>(bng, bnb, l, 1);
        apply_out<<<gridA, 256>>>(out, (l == LAY - 1) ? 1 : 0, (l < LAY - 1) ? 1 : 0);
    }
}

// round 3
// speedup vs baseline: 1.4282x; 1.4282x over previous
#include <cuda_runtime.h>
#include <cuda_bf16.h>
#include <cstdint>

#define NN   100000
#define EE   256000
#define EMB  300
#define EMB2 600
#define LAY  5
#define C75  (EMB / 4)

// ---------------- scratch ----------------
__device__ __align__(128) float g_agg [(size_t)NN * EMB];
__device__ __align__(128) float g_z1  [(size_t)NN * EMB2];
__device__ __align__(128) float g_z2  [(size_t)NN * EMB];
__device__ __align__(128) float g_h   [(size_t)NN * EMB];
__device__ __align__(128) float g_comb[18 * EMB];
__device__ __align__(128) float g_stats[1800];
__device__ __align__(128) float g_scale1[EMB2];
__device__ __align__(128) float g_shift1[EMB2];
__device__ __align__(128) float g_scale2[EMB];
__device__ __align__(128) float g_shift2[EMB];

// ---------------- helpers ----------------
__device__ __forceinline__ uint32_t smem_u32(const void* p) {
    uint32_t a;
    asm("{ .reg .u64 t; cvta.to.shared.u64 t, %1; cvt.u32.u64 %0, t; }" : "=r"(a) : "l"(p));
    return a;
}
__device__ __forceinline__ void ldsm4(uint32_t* r, uint32_t addr) {
    asm volatile("ldmatrix.sync.aligned.m8n8.x4.shared.b16 {%0,%1,%2,%3}, [%4];"
        : "=r"(r[0]), "=r"(r[1]), "=r"(r[2]), "=r"(r[3]) : "r"(addr));
}
__device__ __forceinline__ void mma16816(float* d, const uint32_t* a, uint32_t b0, uint32_t b1) {
    asm volatile("mma.sync.aligned.m16n8k16.row.col.f32.bf16.bf16.f32 "
        "{%0,%1,%2,%3}, {%4,%5,%6,%7}, {%8,%9}, {%0,%1,%2,%3};"
        : "+f"(d[0]), "+f"(d[1]), "+f"(d[2]), "+f"(d[3])
        : "r"(a[0]), "r"(a[1]), "r"(a[2]), "r"(a[3]), "r"(b0), "r"(b1));
}
__device__ __forceinline__ void split2(float x, float y, uint32_t& hi, uint32_t& lo) {
    __nv_bfloat16 hx = __float2bfloat16(x);
    __nv_bfloat16 hy = __float2bfloat16(y);
    float rx = x - __bfloat162float(hx);
    float ry = y - __bfloat162float(hy);
    __nv_bfloat16 lx = __float2bfloat16(rx);
    __nv_bfloat16 ly = __float2bfloat16(ry);
    hi = (uint32_t)__bfloat16_as_ushort(hx) | ((uint32_t)__bfloat16_as_ushort(hy) << 16);
    lo = (uint32_t)__bfloat16_as_ushort(lx) | ((uint32_t)__bfloat16_as_ushort(ly) << 16);
}
// swizzled byte offset within a (rows x 32 bf16) tile stored as 64B rows
__device__ __forceinline__ uint32_t swz(int row, int kb) {
    return (uint32_t)(row * 64 + (((((kb >> 4) & 3) ^ ((row >> 1) & 3))) << 4) + (kb & 15));
}

// ---------------- small kernels ----------------
__global__ void build_comb(const float* __restrict__ Wb, int l) {
    int t = blockIdx.x * 256 + threadIdx.x;
    if (t < 18 * EMB) {
        int p = t / EMB;
        int f = t - p * EMB;
        int a = p / 3, b = p - a * 3;
        const float* w = Wb + (size_t)l * EMB * 9 + (size_t)f * 9;
        g_comb[p * EMB + f] = w[a] + w[6 + b];
    }
}
__global__ void zero_stats() {
    int t = blockIdx.x * 256 + threadIdx.x;
    if (t < 1800) g_stats[t] = 0.0f;
}
__global__ void init_agg(const float* __restrict__ x, int use_x, const float* __restrict__ eps, int l) {
    int i = blockIdx.x * 256 + threadIdx.x;
    if (i < NN * C75) {
        const float4* h = reinterpret_cast<const float4*>(use_x ? x : g_h);
        float s = 1.0f + eps[l];
        float4 v = h[i];
        v.x *= s; v.y *= s; v.z *= s; v.w *= s;
        reinterpret_cast<float4*>(g_agg)[i] = v;
    }
}
__global__ void edge_scatter(const float* __restrict__ x, int use_x,
                             const int* __restrict__ ei, const int* __restrict__ attr) {
    int idx = blockIdx.x * 256 + threadIdx.x;
    if (idx >= EE * C75) return;
    int e = idx / C75;
    int c = idx - e * C75;
    const float* h = use_x ? x : g_h;
    int src = ei[e];
    int dst = ei[EE + e];
    int2 av = *reinterpret_cast<const int2*>(attr + 2 * e);
    float4 hv = *reinterpret_cast<const float4*>(h + (size_t)src * EMB + 4 * c);
    float4 ev = *reinterpret_cast<const float4*>(g_comb + (av.x * 3 + av.y) * EMB + 4 * c);
    float4 m;
    m.x = fmaxf(hv.x + ev.x, 0.0f);
    m.y = fmaxf(hv.y + ev.y, 0.0f);
    m.z = fmaxf(hv.z + ev.z, 0.0f);
    m.w = fmaxf(hv.w + ev.w, 0.0f);
    float* a = g_agg + (size_t)dst * EMB + 4 * c;
    atomicAdd(a + 0, m.x);
    atomicAdd(a + 1, m.y);
    atomicAdd(a + 2, m.z);
    atomicAdd(a + 3, m.w);
}

// ---------------- mma.sync bf16x3 GEMM ----------------
// C[M,Nc] = act(A) @ W^T + bias; W row-major [Nc,K]
// block 128x64, BK=32, 8 warps (4M x 2N), warp tile 32x32
__global__ __launch_bounds__(256, 2)
void gemm_mma(int sel, const float* __restrict__ W, const float* __restrict__ bias,
              int M, int Nc, int K, int nChunks) {
    __shared__ __align__(1024) char sm[24576];
    const uint32_t aHi = smem_u32(sm);
    const uint32_t aLo = aHi + 8192;
    const uint32_t bHi = aHi + 16384;
    const uint32_t bLo = aHi + 20480;

    const int tid = threadIdx.x;
    const int wid = tid >> 5;
    const int lane = tid & 31;
    const int row0 = blockIdx.y * 128;
    const int col0 = blockIdx.x * 64;

    const float* A = sel ? g_z1 : g_agg;
    float* Cout = sel ? g_z2 : g_z1;
    float* statSum = sel ? (g_stats + 1200) : g_stats;
    float* statSq  = sel ? (g_stats + 1500) : (g_stats + 600);

    // per-thread load mapping
    const int ar = tid >> 1;                 // A row 0..127
    const int ah = (tid & 1) * 16;           // A col half
    const int br = tid >> 2;                 // B row 0..63
    const int bq = (tid & 3) * 8;            // B col quarter

    float acc[2][4][4];
#pragma unroll
    for (int i = 0; i < 2; i++)
#pragma unroll
        for (int j = 0; j < 4; j++)
#pragma unroll
            for (int r = 0; r < 4; r++) acc[i][j][r] = 0.f;

    const int wm = wid >> 1;   // 0..3
    const int wn = wid & 1;    // 0..1
    const int wr = wm * 32;
    const int wc = wn * 32;

    float4 vA[4], vB[2];
    // ---- prologue: load chunk 0 ----
    {
        const int grow = row0 + ar;
        const int gcol = col0 + br;
#pragma unroll
        for (int q = 0; q < 4; q++) {
            int gk = ah + q * 4;
            vA[q] = make_float4(0.f, 0.f, 0.f, 0.f);
            if (grow < M && gk + 4 <= K) {
                float4 v = *reinterpret_cast<const float4*>(A + (size_t)grow * K + gk);
                if (sel) {
                    float4 s = *reinterpret_cast<const float4*>(g_scale1 + gk);
                    float4 t = *reinterpret_cast<const float4*>(g_shift1 + gk);
                    v.x = fmaxf(fmaf(v.x, s.x, t.x), 0.f);
                    v.y = fmaxf(fmaf(v.y, s.y, t.y), 0.f);
                    v.z = fmaxf(fmaf(v.z, s.z, t.z), 0.f);
                    v.w = fmaxf(fmaf(v.w, s.w, t.w), 0.f);
                }
                vA[q] = v;
            }
        }
#pragma unroll
        for (int q = 0; q < 2; q++) {
            int gk = bq + q * 4;
            vB[q] = make_float4(0.f, 0.f, 0.f, 0.f);
            if (gcol < Nc && gk + 4 <= K)
                vB[q] = *reinterpret_cast<const float4*>(W + (size_t)gcol * K + gk);
        }
    }

    for (int ch = 0; ch < nChunks; ch++) {
        // ---- store current chunk (split to bf16 hi/lo, swizzled) ----
#pragma unroll
        for (int q = 0; q < 4; q++) {
            uint32_t off = swz(ar, (ah + q * 4) * 2);
            uint2 hi, lo;
            split2(vA[q].x, vA[q].y, hi.x, lo.x);
            split2(vA[q].z, vA[q].w, hi.y, lo.y);
            *reinterpret_cast<uint2*>(sm + off) = hi;
            *reinterpret_cast<uint2*>(sm + 8192 + off) = lo;
        }
#pragma unroll
        for (int q = 0; q < 2; q++) {
            uint32_t off = swz(br, (bq + q * 4) * 2);
            uint2 hi, lo;
            split2(vB[q].x, vB[q].y, hi.x, lo.x);
            split2(vB[q].z, vB[q].w, hi.y, lo.y);
            *reinterpret_cast<uint2*>(sm + 16384 + off) = hi;
            *reinterpret_cast<uint2*>(sm + 20480 + off) = lo;
        }
        __syncthreads();

        // ---- prefetch next chunk into regs ----
        if (ch + 1 < nChunks) {
            const int k0 = (ch + 1) * 32;
            const int grow = row0 + ar;
            const int gcol = col0 + br;
#pragma unroll
            for (int q = 0; q < 4; q++) {
                int gk = k0 + ah + q * 4;
                vA[q] = make_float4(0.f, 0.f, 0.f, 0.f);
                if (grow < M && gk + 4 <= K) {
                    float4 v = *reinterpret_cast<const float4*>(A + (size_t)grow * K + gk);
                    if (sel) {
                        float4 s = *reinterpret_cast<const float4*>(g_scale1 + gk);
                        float4 t = *reinterpret_cast<const float4*>(g_shift1 + gk);
                        v.x = fmaxf(fmaf(v.x, s.x, t.x), 0.f);
                        v.y = fmaxf(fmaf(v.y, s.y, t.y), 0.f);
                        v.z = fmaxf(fmaf(v.z, s.z, t.z), 0.f);
                        v.w = fmaxf(fmaf(v.w, s.w, t.w), 0.f);
                    }
                    vA[q] = v;
                }
            }
#pragma unroll
            for (int q = 0; q < 2; q++) {
                int gk = k0 + bq + q * 4;
                vB[q] = make_float4(0.f, 0.f, 0.f, 0.f);
                if (gcol < Nc && gk + 4 <= K)
                    vB[q] = *reinterpret_cast<const float4*>(W + (size_t)gcol * K + gk);
            }
        }

        // ---- compute current chunk from smem ----
#pragma unroll
        for (int ks = 0; ks < 2; ks++) {
            const int kb = ks * 32 + ((lane >> 4) << 4);
            uint32_t ahi[2][4], alo[2][4];
#pragma unroll
            for (int i = 0; i < 2; i++) {
                uint32_t off = swz(wr + i * 16 + (lane & 15), kb);
                ldsm4(ahi[i], aHi + off);
                ldsm4(alo[i], aLo + off);
            }
#pragma unroll
            for (int jj = 0; jj < 2; jj++) {
                int rn = wc + jj * 16 + ((lane >> 3) & 1) * 8 + (lane & 7);
                uint32_t off = swz(rn, kb);
                uint32_t bh[4], bl[4];
                ldsm4(bh, bHi + off);
                ldsm4(bl, bLo + off);
#pragma unroll
                for (int i = 0; i < 2; i++) {
                    mma16816(acc[i][2 * jj],     ahi[i], bh[0], bh[2]);
                    mma16816(acc[i][2 * jj + 1], ahi[i], bh[1], bh[3]);
                    mma16816(acc[i][2 * jj],     ahi[i], bl[0], bl[2]);
                    mma16816(acc[i][2 * jj + 1], ahi[i], bl[1], bl[3]);
                    mma16816(acc[i][2 * jj],     alo[i], bh[0], bh[2]);
                    mma16816(acc[i][2 * jj + 1], alo[i], bh[1], bh[3]);
                }
            }
        }
        __syncthreads();
    }

    // ---- epilogue: bias + store + BN stats ----
    float* sSum = reinterpret_cast<float*>(sm);
    float* sSq  = sSum + 64;
    if (tid < 64) { sSum[tid] = 0.f; sSq[tid] = 0.f; }
    __syncthreads();

    const int g  = lane >> 2;
    const int tg = lane & 3;
    float bv[8];
#pragma unroll
    for (int j = 0; j < 4; j++) {
        int gc = col0 + wc + j * 8 + tg * 2;
        bool cv = gc < Nc;
        bv[2 * j]     = cv ? bias[gc] : 0.f;
        bv[2 * j + 1] = cv ? bias[gc + 1] : 0.f;
    }
    float csum[8], csq[8];
#pragma unroll
    for (int k = 0; k < 8; k++) { csum[k] = 0.f; csq[k] = 0.f; }

#pragma unroll
    for (int i = 0; i < 2; i++) {
        int ra = row0 + wr + i * 16 + g;
        int rb = ra + 8;
#pragma unroll
        for (int j = 0; j < 4; j++) {
            int gc = col0 + wc + j * 8 + tg * 2;
            if (gc < Nc) {
                float o0 = acc[i][j][0] + bv[2 * j];
                float o1 = acc[i][j][1] + bv[2 * j + 1];
                if (ra < M) {
                    *reinterpret_cast<float2*>(Cout + (size_t)ra * Nc + gc) = make_float2(o0, o1);
                    csum[2 * j] += o0; csum[2 * j + 1] += o1;
                    csq[2 * j] += o0 * o0; csq[2 * j + 1] += o1 * o1;
                }
                float o2 = acc[i][j][2] + bv[2 * j];
                float o3 = acc[i][j][3] + bv[2 * j + 1];
                if (rb < M) {
                    *reinterpret_cast<float2*>(Cout + (size_t)rb * Nc + gc) = make_float2(o2, o3);
                    csum[2 * j] += o2; csum[2 * j + 1] += o3;
                    csq[2 * j] += o2 * o2; csq[2 * j + 1] += o3 * o3;
                }
            }
        }
    }
    // reduce across lanes sharing the same columns (xor 4, 8, 16)
#pragma unroll
    for (int off = 4; off <= 16; off <<= 1) {
#pragma unroll
        for (int k = 0; k < 8; k++) {
            csum[k] += __shfl_xor_sync(0xffffffffu, csum[k], off);
            csq[k]  += __shfl_xor_sync(0xffffffffu, csq[k], off);
        }
    }
    if (lane < 4) {
#pragma unroll
        for (int j = 0; j < 4; j++) {
            int c = wc + j * 8 + lane * 2;
            if (col0 + c < Nc) {
                atomicAdd(&sSum[c], csum[2 * j]);
                atomicAdd(&sSum[c + 1], csum[2 * j + 1]);
                atomicAdd(&sSq[c], csq[2 * j]);
                atomicAdd(&sSq[c + 1], csq[2 * j + 1]);
            }
        }
    }
    __syncthreads();
    if (tid < 64 && col0 + tid < Nc) {
        atomicAdd(statSum + col0 + tid, sSum[tid]);
        atomicAdd(statSq + col0 + tid, sSq[tid]);
    }
}

__global__ void finalize_bn(const float* __restrict__ gamma, const float* __restrict__ beta,
                            int l, int sel) {
    int Ccols = sel ? EMB : EMB2;
    const float* sum = sel ? (g_stats + 1200) : g_stats;
    const float* sq  = sel ? (g_stats + 1500) : (g_stats + 600);
    float* scale = sel ? g_scale2 : g_scale1;
    float* shift = sel ? g_shift2 : g_shift1;
    int j = blockIdx.x * 256 + threadIdx.x;
    if (j < Ccols) {
        float inv = 1.0f / (float)NN;
        float m = sum[j] * inv;
        float v = sq[j] * inv - m * m;
        float sc = gamma[l * Ccols + j] * rsqrtf(v + 1e-5f);
        scale[j] = sc;
        shift[j] = beta[l * Ccols + j] - m * sc;
    }
}

__global__ void apply_out(float* __restrict__ dout, int use_dout, int do_relu) {
    int i = blockIdx.x * 256 + threadIdx.x;
    if (i < NN * C75) {
        int c4 = (i % C75) * 4;
        float4 v = reinterpret_cast<const float4*>(g_z2)[i];
        float4 sc = *reinterpret_cast<const float4*>(g_scale2 + c4);
        float4 sh = *reinterpret_cast<const float4*>(g_shift2 + c4);
        v.x = fmaf(v.x, sc.x, sh.x);
        v.y = fmaf(v.y, sc.y, sh.y);
        v.z = fmaf(v.z, sc.z, sh.z);
        v.w = fmaf(v.w, sc.w, sh.w);
        if (do_relu) {
            v.x = fmaxf(v.x, 0.f);
            v.y = fmaxf(v.y, 0.f);
            v.z = fmaxf(v.z, 0.f);
            v.w = fmaxf(v.w, 0.f);
        }
        float4* o = use_dout ? reinterpret_cast<float4*>(dout) : reinterpret_cast<float4*>(g_h);
        o[i] = v;
    }
}

// ---------------- host ----------------
extern "C" void kernel_launch(void* const* d_in, const int* in_sizes, int n_in,
                              void* d_out, int out_size) {
    const float* x    = (const float*)d_in[0];
    const float* Wb   = (const float*)d_in[1];
    const float* eps  = (const float*)d_in[2];
    const float* W1   = (const float*)d_in[3];
    const float* b1   = (const float*)d_in[4];
    const float* bn1g = (const float*)d_in[5];
    const float* bn1b = (const float*)d_in[6];
    const float* W2   = (const float*)d_in[7];
    const float* b2   = (const float*)d_in[8];
    const float* bng  = (const float*)d_in[9];
    const float* bnb  = (const float*)d_in[10];
    const int*   ei   = (const int*)d_in[11];
    const int*   attr = (const int*)d_in[12];
    float* out = (float*)d_out;

    const int gridA = (NN * C75 + 255) / 256;
    const int gridE = (EE * C75 + 255) / 256;
    const int rowT  = (NN + 127) / 128;        // 782
    const int cb1   = (EMB2 + 63) / 64;        // 10
    const int cb2   = (EMB + 63) / 64;         // 5
    const int nch1  = (EMB + 31) / 32;         // 10
    const int nch2  = (EMB2 + 31) / 32;        // 19

    for (int l = 0; l < LAY; l++) {
        int use_x = (l == 0) ? 1 : 0;
        build_comb<<<(18 * EMB + 255) / 256, 256>>>(Wb, l);
        zero_stats<<<(1800 + 255) / 256, 256>>>();
        init_agg<<<gridA, 256>>>(x, use_x, eps, l);
        edge_scatter<<<gridE, 256>>>(x, use_x, ei, attr);
        gemm_mma<<<dim3(cb1, rowT), 256>>>(0, W1 + (size_t)l * EMB2 * EMB, b1 + l * EMB2,
                                           NN, EMB2, EMB, nch1);
        finalize_bn<<<(EMB2 + 255) / 256, 256>>>(bn1g, bn1b, l, 0);
        gemm_mma<<<dim3(cb2, rowT), 256>>>(1, W2 + (size_t)l * EMB * EMB2, b2 + l * EMB,
                                           NN, EMB, EMB2, nch2);
        finalize_bn<<<(EMB + 255) / 256, 256>>>(bng, bnb, l, 1);
        apply_out<<<gridA, 256>>>(out, (l == LAY - 1) ? 1 : 0, (l < LAY - 1) ? 1 : 0);
    }
}

// round 7
// speedup vs baseline: 1.6669x; 1.1671x over previous
#include <cuda_runtime.h>
#include <cuda_bf16.h>
#include <cstdint>

#define NN   100000
#define EE   256000
#define EMB  300
#define EMB2 600
#define LAY  5
#define C75  (EMB / 4)
#define KP1  320   // padded K for GEMM1 (K=300)
#define KP2  608   // padded K for GEMM2 (K=600)

// ---------------- scratch ----------------
__device__ __align__(128) float g_agg [(size_t)NN * EMB];
__device__ __align__(128) float g_z1  [(size_t)NN * EMB2];
__device__ __align__(128) float g_z2  [(size_t)NN * EMB];
__device__ __align__(128) float g_h   [(size_t)NN * EMB];
__device__ __align__(128) float g_comb[18 * EMB];
__device__ __align__(128) float g_stats[1800];
__device__ __align__(128) float g_scale1[EMB2];
__device__ __align__(128) float g_shift1[EMB2];
__device__ __align__(128) float g_scale2[EMB];
__device__ __align__(128) float g_shift2[EMB];
// bf16 split planes (padded K)
__device__ __align__(128) __nv_bfloat16 g_aggH[(size_t)NN * KP1];
__device__ __align__(128) __nv_bfloat16 g_aggL[(size_t)NN * KP1];
__device__ __align__(128) __nv_bfloat16 g_z1aH[(size_t)NN * KP2];
__device__ __align__(128) __nv_bfloat16 g_z1aL[(size_t)NN * KP2];
__device__ __align__(128) __nv_bfloat16 g_w1H[EMB2 * KP1];
__device__ __align__(128) __nv_bfloat16 g_w1L[EMB2 * KP1];
__device__ __align__(128) __nv_bfloat16 g_w2H[EMB * KP2];
__device__ __align__(128) __nv_bfloat16 g_w2L[EMB * KP2];

// ---------------- helpers ----------------
__device__ __forceinline__ uint32_t smem_u32(const void* p) {
    uint32_t a;
    asm("{ .reg .u64 t; cvta.to.shared.u64 t, %1; cvt.u32.u64 %0, t; }" : "=r"(a) : "l"(p));
    return a;
}
__device__ __forceinline__ void ldsm4(uint32_t* r, uint32_t addr) {
    asm volatile("ldmatrix.sync.aligned.m8n8.x4.shared.b16 {%0,%1,%2,%3}, [%4];"
        : "=r"(r[0]), "=r"(r[1]), "=r"(r[2]), "=r"(r[3]) : "r"(addr));
}
__device__ __forceinline__ void mma16816(float* d, const uint32_t* a, uint32_t b0, uint32_t b1) {
    asm volatile("mma.sync.aligned.m16n8k16.row.col.f32.bf16.bf16.f32 "
        "{%0,%1,%2,%3}, {%4,%5,%6,%7}, {%8,%9}, {%0,%1,%2,%3};"
        : "+f"(d[0]), "+f"(d[1]), "+f"(d[2]), "+f"(d[3])
        : "r"(a[0]), "r"(a[1]), "r"(a[2]), "r"(a[3]), "r"(b0), "r"(b1));
}
__device__ __forceinline__ void split2(float x, float y, uint32_t& hi, uint32_t& lo) {
    __nv_bfloat16 hx = __float2bfloat16(x);
    __nv_bfloat16 hy = __float2bfloat16(y);
    float rx = x - __bfloat162float(hx);
    float ry = y - __bfloat162float(hy);
    __nv_bfloat16 lx = __float2bfloat16(rx);
    __nv_bfloat16 ly = __float2bfloat16(ry);
    hi = (uint32_t)__bfloat16_as_ushort(hx) | ((uint32_t)__bfloat16_as_ushort(hy) << 16);
    lo = (uint32_t)__bfloat16_as_ushort(lx) | ((uint32_t)__bfloat16_as_ushort(ly) << 16);
}
__device__ __forceinline__ uint32_t swz(int row, int kb) {
    return (uint32_t)(row * 64 + (((((kb >> 4) & 3) ^ ((row >> 1) & 3))) << 4) + (kb & 15));
}

// ---------------- small kernels ----------------
__global__ void build_comb(const float* __restrict__ Wb, int l) {
    int t = blockIdx.x * 256 + threadIdx.x;
    if (t < 18 * EMB) {
        int p = t / EMB;
        int f = t - p * EMB;
        int a = p / 3, b = p - a * 3;
        const float* w = Wb + (size_t)l * EMB * 9 + (size_t)f * 9;
        g_comb[p * EMB + f] = w[a] + w[6 + b];
    }
}
__global__ void zero_stats() {
    int t = blockIdx.x * 256 + threadIdx.x;
    if (t < 1800) g_stats[t] = 0.0f;
}
__global__ void init_agg(const float* __restrict__ x, int use_x, const float* __restrict__ eps, int l) {
    int i = blockIdx.x * 256 + threadIdx.x;
    if (i < NN * C75) {
        const float4* h = reinterpret_cast<const float4*>(use_x ? x : g_h);
        float s = 1.0f + eps[l];
        float4 v = h[i];
        v.x *= s; v.y *= s; v.z *= s; v.w *= s;
        reinterpret_cast<float4*>(g_agg)[i] = v;
    }
}
__global__ void edge_scatter(const float* __restrict__ x, int use_x,
                             const int* __restrict__ ei, const int* __restrict__ attr) {
    int idx = blockIdx.x * 256 + threadIdx.x;
    if (idx >= EE * C75) return;
    int e = idx / C75;
    int c = idx - e * C75;
    const float* h = use_x ? x : g_h;
    int src = ei[e];
    int dst = ei[EE + e];
    int2 av = *reinterpret_cast<const int2*>(attr + 2 * e);
    float4 hv = *reinterpret_cast<const float4*>(h + (size_t)src * EMB + 4 * c);
    float4 ev = *reinterpret_cast<const float4*>(g_comb + (av.x * 3 + av.y) * EMB + 4 * c);
    float4 m;
    m.x = fmaxf(hv.x + ev.x, 0.0f);
    m.y = fmaxf(hv.y + ev.y, 0.0f);
    m.z = fmaxf(hv.z + ev.z, 0.0f);
    m.w = fmaxf(hv.w + ev.w, 0.0f);
    float* a = g_agg + (size_t)dst * EMB + 4 * c;
    atomicAdd(a + 0, m.x);
    atomicAdd(a + 1, m.y);
    atomicAdd(a + 2, m.z);
    atomicAdd(a + 3, m.w);
}

// ---------------- split to bf16 hi/lo planes ----------------
// srcsel: 0 = external ptr (weights), 1 = g_agg, 2 = g_z1 (with bn1+relu transform)
// dstsel: 0 = (g_aggH, g_aggL), 1 = (g_z1aH, g_z1aL), 2 = (g_w1H, g_w1L), 3 = (g_w2H, g_w2L)
// NOTE: plane destinations are resolved in DEVICE code — __device__ symbol
// addresses must never be passed from host.
__global__ void split_fp32(const float* __restrict__ xsrc, int srcsel, int dstsel,
                           int rows, int K, int Kp) {
    const float* src = (srcsel == 1) ? g_agg : ((srcsel == 2) ? g_z1 : xsrc);
    __nv_bfloat16 *hi, *lo;
    switch (dstsel) {
        case 0:  hi = g_aggH; lo = g_aggL; break;
        case 1:  hi = g_z1aH; lo = g_z1aL; break;
        case 2:  hi = g_w1H;  lo = g_w1L;  break;
        default: hi = g_w2H;  lo = g_w2L;  break;
    }
    const int c8n = Kp >> 3;
    int idx = blockIdx.x * 256 + threadIdx.x;
    if (idx >= rows * c8n) return;
    int r = idx / c8n;
    int c8 = (idx - r * c8n) << 3;
    float v[8];
    const float* p = src + (size_t)r * K + c8;
    if (c8 + 8 <= K) {
        float4 a = *reinterpret_cast<const float4*>(p);
        float4 b = *reinterpret_cast<const float4*>(p + 4);
        v[0] = a.x; v[1] = a.y; v[2] = a.z; v[3] = a.w;
        v[4] = b.x; v[5] = b.y; v[6] = b.z; v[7] = b.w;
    } else {
#pragma unroll
        for (int j = 0; j < 8; j++) v[j] = (c8 + j < K) ? p[j] : 0.f;
    }
    if (srcsel == 2) {
#pragma unroll
        for (int j = 0; j < 8; j++)
            v[j] = (c8 + j < K) ? fmaxf(fmaf(v[j], g_scale1[c8 + j], g_shift1[c8 + j]), 0.f) : 0.f;
    }
    uint4 h4, l4;
    split2(v[0], v[1], h4.x, l4.x);
    split2(v[2], v[3], h4.y, l4.y);
    split2(v[4], v[5], h4.z, l4.z);
    split2(v[6], v[7], h4.w, l4.w);
    *reinterpret_cast<uint4*>(hi + (size_t)r * Kp + c8) = h4;
    *reinterpret_cast<uint4*>(lo + (size_t)r * Kp + c8) = l4;
}

// ---------------- bf16x3 GEMM from pre-split planes ----------------
// block 128x64, BK=32, 8 warps (4M x 2N), warp tile 32x32
// smem: AH[8192] AL[8192] BH[4096] BL[4096] = 24576B, single buffer + reg prefetch
__global__ __launch_bounds__(256, 2)
void gemm_bf16(int sel, const float* __restrict__ bias, int M, int Nc, int nChunks) {
    __shared__ __align__(1024) char sm[24576];
    const uint32_t aHi = smem_u32(sm);
    const uint32_t aLo = aHi + 8192;
    const uint32_t bHi = aHi + 16384;
    const uint32_t bLo = aHi + 20480;

    const __nv_bfloat16 *Ah, *Al, *Bh, *Bl;
    int ldk;
    float *Cout, *statSum, *statSq;
    if (sel == 0) {
        Ah = g_aggH; Al = g_aggL; Bh = g_w1H; Bl = g_w1L; ldk = KP1;
        Cout = g_z1; statSum = g_stats; statSq = g_stats + 600;
    } else {
        Ah = g_z1aH; Al = g_z1aL; Bh = g_w2H; Bl = g_w2L; ldk = KP2;
        Cout = g_z2; statSum = g_stats + 1200; statSq = g_stats + 1500;
    }

    const int tid = threadIdx.x;
    const int wid = tid >> 5;
    const int lane = tid & 31;
    const int row0 = blockIdx.y * 128;
    const int col0 = blockIdx.x * 64;

    const int la_r = tid >> 1;
    const int la_e = (tid & 1) * 16;
    const int lb_r = tid >> 2;
    const int lb_e = (tid & 3) * 8;

    const bool aok = (row0 + la_r) < M;
    const bool bok = (col0 + lb_r) < Nc;
    const __nv_bfloat16* pA_h = Ah + (size_t)(aok ? row0 + la_r : 0) * ldk + la_e;
    const __nv_bfloat16* pA_l = Al + (size_t)(aok ? row0 + la_r : 0) * ldk + la_e;
    const __nv_bfloat16* pB_h = Bh + (size_t)(bok ? col0 + lb_r : 0) * ldk + lb_e;
    const __nv_bfloat16* pB_l = Bl + (size_t)(bok ? col0 + lb_r : 0) * ldk + lb_e;

    float acc[2][4][4];
#pragma unroll
    for (int i = 0; i < 2; i++)
#pragma unroll
        for (int j = 0; j < 4; j++)
#pragma unroll
            for (int r = 0; r < 4; r++) acc[i][j][r] = 0.f;

    const int wm = wid >> 1;
    const int wn = wid & 1;
    const int wr = wm * 32;
    const int wc = wn * 32;

    const uint4 Z = make_uint4(0u, 0u, 0u, 0u);
    uint4 vAh0, vAh1, vAl0, vAl1, vBh, vBl;

    vAh0 = aok ? *reinterpret_cast<const uint4*>(pA_h)     : Z;
    vAh1 = aok ? *reinterpret_cast<const uint4*>(pA_h + 8) : Z;
    vAl0 = aok ? *reinterpret_cast<const uint4*>(pA_l)     : Z;
    vAl1 = aok ? *reinterpret_cast<const uint4*>(pA_l + 8) : Z;
    vBh  = bok ? *reinterpret_cast<const uint4*>(pB_h)     : Z;
    vBl  = bok ? *reinterpret_cast<const uint4*>(pB_l)     : Z;

    const uint32_t offA0 = swz(la_r, la_e * 2);
    const uint32_t offA1 = swz(la_r, la_e * 2 + 16);
    const uint32_t offB  = swz(lb_r, lb_e * 2);

    for (int ch = 0; ch < nChunks; ch++) {
        *reinterpret_cast<uint4*>(sm + offA0) = vAh0;
        *reinterpret_cast<uint4*>(sm + offA1) = vAh1;
        *reinterpret_cast<uint4*>(sm + 8192 + offA0) = vAl0;
        *reinterpret_cast<uint4*>(sm + 8192 + offA1) = vAl1;
        *reinterpret_cast<uint4*>(sm + 16384 + offB) = vBh;
        *reinterpret_cast<uint4*>(sm + 20480 + offB) = vBl;
        __syncthreads();

        if (ch + 1 < nChunks) {
            const int k0 = (ch + 1) * 32;
            vAh0 = aok ? *reinterpret_cast<const uint4*>(pA_h + k0)     : Z;
            vAh1 = aok ? *reinterpret_cast<const uint4*>(pA_h + k0 + 8) : Z;
            vAl0 = aok ? *reinterpret_cast<const uint4*>(pA_l + k0)     : Z;
            vAl1 = aok ? *reinterpret_cast<const uint4*>(pA_l + k0 + 8) : Z;
            vBh  = bok ? *reinterpret_cast<const uint4*>(pB_h + k0)     : Z;
            vBl  = bok ? *reinterpret_cast<const uint4*>(pB_l + k0)     : Z;
        }

#pragma unroll
        for (int ks = 0; ks < 2; ks++) {
            const int kb = ks * 32 + ((lane >> 4) << 4);
            uint32_t ahi[2][4], alo[2][4];
#pragma unroll
            for (int i = 0; i < 2; i++) {
                uint32_t off = swz(wr + i * 16 + (lane & 15), kb);
                ldsm4(ahi[i], aHi + off);
                ldsm4(alo[i], aLo + off);
            }
#pragma unroll
            for (int jj = 0; jj < 2; jj++) {
                int rn = wc + jj * 16 + ((lane >> 3) & 1) * 8 + (lane & 7);
                uint32_t off = swz(rn, kb);
                uint32_t bh[4], bl[4];
                ldsm4(bh, bHi + off);
                ldsm4(bl, bLo + off);
#pragma unroll
                for (int i = 0; i < 2; i++) {
                    mma16816(acc[i][2 * jj],     ahi[i], bh[0], bh[2]);
                    mma16816(acc[i][2 * jj + 1], ahi[i], bh[1], bh[3]);
                    mma16816(acc[i][2 * jj],     ahi[i], bl[0], bl[2]);
                    mma16816(acc[i][2 * jj + 1], ahi[i], bl[1], bl[3]);
                    mma16816(acc[i][2 * jj],     alo[i], bh[0], bh[2]);
                    mma16816(acc[i][2 * jj + 1], alo[i], bh[1], bh[3]);
                }
            }
        }
        __syncthreads();
    }

    // ---- epilogue: bias + store + BN stats ----
    float* sSum = reinterpret_cast<float*>(sm);
    float* sSq  = sSum + 64;
    if (tid < 64) { sSum[tid] = 0.f; sSq[tid] = 0.f; }
    __syncthreads();

    const int g  = lane >> 2;
    const int tg = lane & 3;
    float bv[8];
#pragma unroll
    for (int j = 0; j < 4; j++) {
        int gc = col0 + wc + j * 8 + tg * 2;
        bool cv = gc < Nc;
        bv[2 * j]     = cv ? bias[gc] : 0.f;
        bv[2 * j + 1] = cv ? bias[gc + 1] : 0.f;
    }
    float csum[8], csq[8];
#pragma unroll
    for (int k = 0; k < 8; k++) { csum[k] = 0.f; csq[k] = 0.f; }

#pragma unroll
    for (int i = 0; i < 2; i++) {
        int ra = row0 + wr + i * 16 + g;
        int rb = ra + 8;
#pragma unroll
        for (int j = 0; j < 4; j++) {
            int gc = col0 + wc + j * 8 + tg * 2;
            if (gc < Nc) {
                float o0 = acc[i][j][0] + bv[2 * j];
                float o1 = acc[i][j][1] + bv[2 * j + 1];
                if (ra < M) {
                    *reinterpret_cast<float2*>(Cout + (size_t)ra * Nc + gc) = make_float2(o0, o1);
                    csum[2 * j] += o0; csum[2 * j + 1] += o1;
                    csq[2 * j] += o0 * o0; csq[2 * j + 1] += o1 * o1;
                }
                float o2 = acc[i][j][2] + bv[2 * j];
                float o3 = acc[i][j][3] + bv[2 * j + 1];
                if (rb < M) {
                    *reinterpret_cast<float2*>(Cout + (size_t)rb * Nc + gc) = make_float2(o2, o3);
                    csum[2 * j] += o2; csum[2 * j + 1] += o3;
                    csq[2 * j] += o2 * o2; csq[2 * j + 1] += o3 * o3;
                }
            }
        }
    }
#pragma unroll
    for (int off = 4; off <= 16; off <<= 1) {
#pragma unroll
        for (int k = 0; k < 8; k++) {
            csum[k] += __shfl_xor_sync(0xffffffffu, csum[k], off);
            csq[k]  += __shfl_xor_sync(0xffffffffu, csq[k], off);
        }
    }
    if (lane < 4) {
#pragma unroll
        for (int j = 0; j < 4; j++) {
            int c = wc + j * 8 + lane * 2;
            if (col0 + c < Nc) {
                atomicAdd(&sSum[c], csum[2 * j]);
                atomicAdd(&sSum[c + 1], csum[2 * j + 1]);
                atomicAdd(&sSq[c], csq[2 * j]);
                atomicAdd(&sSq[c + 1], csq[2 * j + 1]);
            }
        }
    }
    __syncthreads();
    if (tid < 64 && col0 + tid < Nc) {
        atomicAdd(statSum + col0 + tid, sSum[tid]);
        atomicAdd(statSq + col0 + tid, sSq[tid]);
    }
}

__global__ void finalize_bn(const float* __restrict__ gamma, const float* __restrict__ beta,
                            int l, int sel) {
    int Ccols = sel ? EMB : EMB2;
    const float* sum = sel ? (g_stats + 1200) : g_stats;
    const float* sq  = sel ? (g_stats + 1500) : (g_stats + 600);
    float* scale = sel ? g_scale2 : g_scale1;
    float* shift = sel ? g_shift2 : g_shift1;
    int j = blockIdx.x * 256 + threadIdx.x;
    if (j < Ccols) {
        float inv = 1.0f / (float)NN;
        float m = sum[j] * inv;
        float v = sq[j] * inv - m * m;
        float sc = gamma[l * Ccols + j] * rsqrtf(v + 1e-5f);
        scale[j] = sc;
        shift[j] = beta[l * Ccols + j] - m * sc;
    }
}

__global__ void apply_out(float* __restrict__ dout, int use_dout, int do_relu) {
    int i = blockIdx.x * 256 + threadIdx.x;
    if (i < NN * C75) {
        int c4 = (i % C75) * 4;
        float4 v = reinterpret_cast<const float4*>(g_z2)[i];
        float4 sc = *reinterpret_cast<const float4*>(g_scale2 + c4);
        float4 sh = *reinterpret_cast<const float4*>(g_shift2 + c4);
        v.x = fmaf(v.x, sc.x, sh.x);
        v.y = fmaf(v.y, sc.y, sh.y);
        v.z = fmaf(v.z, sc.z, sh.z);
        v.w = fmaf(v.w, sc.w, sh.w);
        if (do_relu) {
            v.x = fmaxf(v.x, 0.f);
            v.y = fmaxf(v.y, 0.f);
            v.z = fmaxf(v.z, 0.f);
            v.w = fmaxf(v.w, 0.f);
        }
        float4* o = use_dout ? reinterpret_cast<float4*>(dout) : reinterpret_cast<float4*>(g_h);
        o[i] = v;
    }
}

// ---------------- host ----------------
extern "C" void kernel_launch(void* const* d_in, const int* in_sizes, int n_in,
                              void* d_out, int out_size) {
    const float* x    = (const float*)d_in[0];
    const float* Wb   = (const float*)d_in[1];
    const float* eps  = (const float*)d_in[2];
    const float* W1   = (const float*)d_in[3];
    const float* b1   = (const float*)d_in[4];
    const float* bn1g = (const float*)d_in[5];
    const float* bn1b = (const float*)d_in[6];
    const float* W2   = (const float*)d_in[7];
    const float* b2   = (const float*)d_in[8];
    const float* bng  = (const float*)d_in[9];
    const float* bnb  = (const float*)d_in[10];
    const int*   ei   = (const int*)d_in[11];
    const int*   attr = (const int*)d_in[12];
    float* out = (float*)d_out;

    const int gridA = (NN * C75 + 255) / 256;
    const int gridE = (EE * C75 + 255) / 256;
    const int rowT  = (NN + 127) / 128;            // 782
    const int cb1   = (EMB2 + 63) / 64;            // 10
    const int cb2   = (EMB + 63) / 64;             // 5
    const int nch1  = KP1 / 32;                    // 10
    const int nch2  = KP2 / 32;                    // 19
    const int gsA   = (NN * (KP1 / 8) + 255) / 256;
    const int gsZ   = (NN * (KP2 / 8) + 255) / 256;
    const int gsW1  = (EMB2 * (KP1 / 8) + 255) / 256;
    const int gsW2  = (EMB * (KP2 / 8) + 255) / 256;

    for (int l = 0; l < LAY; l++) {
        int use_x = (l == 0) ? 1 : 0;
        build_comb<<<(18 * EMB + 255) / 256, 256>>>(Wb, l);
        zero_stats<<<(1800 + 255) / 256, 256>>>();
        init_agg<<<gridA, 256>>>(x, use_x, eps, l);
        edge_scatter<<<gridE, 256>>>(x, use_x, ei, attr);
        split_fp32<<<gsA, 256>>>(nullptr, 1, 0, NN, EMB, KP1);
        split_fp32<<<gsW1, 256>>>(W1 + (size_t)l * EMB2 * EMB, 0, 2, EMB2, EMB, KP1);
        gemm_bf16<<<dim3(cb1, rowT), 256>>>(0, b1 + l * EMB2, NN, EMB2, nch1);
        finalize_bn<<<(EMB2 + 255) / 256, 256>>>(bn1g, bn1b, l, 0);
        split_fp32<<<gsZ, 256>>>(nullptr, 2, 1, NN, EMB2, KP2);
        split_fp32<<<gsW2, 256>>>(W2 + (size_t)l * EMB * EMB2, 0, 3, EMB, EMB2, KP2);
        gemm_bf16<<<dim3(cb2, rowT), 256>>>(1, b2 + l * EMB, NN, EMB, nch2);
        finalize_bn<<<(EMB + 255) / 256, 256>>>(bng, bnb, l, 1);
        apply_out<<<gridA, 256>>>(out, (l == LAY - 1) ? 1 : 0, (l < LAY - 1) ? 1 : 0);
    }
}

// round 8
// speedup vs baseline: 1.8583x; 1.1148x over previous
#include <cuda_runtime.h>
#include <cuda_bf16.h>
#include <cstdint>

#define NN   100000
#define EE   256000
#define EMB  300
#define EMB2 600
#define LAY  5
#define C75  (EMB / 4)
#define KP1  320   // padded K for GEMM1 (K=300)
#define KP2  608   // padded K for GEMM2 (K=600)

#define STAGE_BYTES 24576
#define NSTAGES 3
#define GEMM_SMEM (STAGE_BYTES * NSTAGES)

// ---------------- scratch ----------------
__device__ __align__(128) float g_agg [(size_t)NN * EMB];
__device__ __align__(128) float g_z1  [(size_t)NN * EMB2];
__device__ __align__(128) float g_z2  [(size_t)NN * EMB];
__device__ __align__(128) float g_h   [(size_t)NN * EMB];
__device__ __align__(128) float g_comb[18 * EMB];
__device__ __align__(128) float g_stats[1800];
__device__ __align__(128) float g_scale1[EMB2];
__device__ __align__(128) float g_shift1[EMB2];
__device__ __align__(128) float g_scale2[EMB];
__device__ __align__(128) float g_shift2[EMB];
// bf16 split planes (padded K)
__device__ __align__(128) __nv_bfloat16 g_aggH[(size_t)NN * KP1];
__device__ __align__(128) __nv_bfloat16 g_aggL[(size_t)NN * KP1];
__device__ __align__(128) __nv_bfloat16 g_z1aH[(size_t)NN * KP2];
__device__ __align__(128) __nv_bfloat16 g_z1aL[(size_t)NN * KP2];
__device__ __align__(128) __nv_bfloat16 g_w1H[EMB2 * KP1];
__device__ __align__(128) __nv_bfloat16 g_w1L[EMB2 * KP1];
__device__ __align__(128) __nv_bfloat16 g_w2H[EMB * KP2];
__device__ __align__(128) __nv_bfloat16 g_w2L[EMB * KP2];

// ---------------- helpers ----------------
__device__ __forceinline__ uint32_t smem_u32(const void* p) {
    uint32_t a;
    asm("{ .reg .u64 t; cvta.to.shared.u64 t, %1; cvt.u32.u64 %0, t; }" : "=r"(a) : "l"(p));
    return a;
}
__device__ __forceinline__ void ldsm4(uint32_t* r, uint32_t addr) {
    asm volatile("ldmatrix.sync.aligned.m8n8.x4.shared.b16 {%0,%1,%2,%3}, [%4];"
        : "=r"(r[0]), "=r"(r[1]), "=r"(r[2]), "=r"(r[3]) : "r"(addr));
}
__device__ __forceinline__ void mma16816(float* d, const uint32_t* a, uint32_t b0, uint32_t b1) {
    asm volatile("mma.sync.aligned.m16n8k16.row.col.f32.bf16.bf16.f32 "
        "{%0,%1,%2,%3}, {%4,%5,%6,%7}, {%8,%9}, {%0,%1,%2,%3};"
        : "+f"(d[0]), "+f"(d[1]), "+f"(d[2]), "+f"(d[3])
        : "r"(a[0]), "r"(a[1]), "r"(a[2]), "r"(a[3]), "r"(b0), "r"(b1));
}
__device__ __forceinline__ void split2(float x, float y, uint32_t& hi, uint32_t& lo) {
    __nv_bfloat16 hx = __float2bfloat16(x);
    __nv_bfloat16 hy = __float2bfloat16(y);
    float rx = x - __bfloat162float(hx);
    float ry = y - __bfloat162float(hy);
    __nv_bfloat16 lx = __float2bfloat16(rx);
    __nv_bfloat16 ly = __float2bfloat16(ry);
    hi = (uint32_t)__bfloat16_as_ushort(hx) | ((uint32_t)__bfloat16_as_ushort(hy) << 16);
    lo = (uint32_t)__bfloat16_as_ushort(lx) | ((uint32_t)__bfloat16_as_ushort(ly) << 16);
}
__device__ __forceinline__ uint32_t swz(int row, int kb) {
    return (uint32_t)(row * 64 + (((((kb >> 4) & 3) ^ ((row >> 1) & 3))) << 4) + (kb & 15));
}
__device__ __forceinline__ void cp16(uint32_t dst, const void* src, bool valid) {
    int sz = valid ? 16 : 0;
    asm volatile("cp.async.cg.shared.global [%0], [%1], 16, %2;"
        :: "r"(dst), "l"(src), "r"(sz) : "memory");
}
#define CP_COMMIT asm volatile("cp.async.commit_group;" ::: "memory")
#define CP_WAIT1  asm volatile("cp.async.wait_group 1;" ::: "memory")
#define CP_WAIT0  asm volatile("cp.async.wait_group 0;" ::: "memory")

// ---------------- small kernels ----------------
__global__ void build_comb(const float* __restrict__ Wb, int l) {
    int t = blockIdx.x * 256 + threadIdx.x;
    if (t < 18 * EMB) {
        int p = t / EMB;
        int f = t - p * EMB;
        int a = p / 3, b = p - a * 3;
        const float* w = Wb + (size_t)l * EMB * 9 + (size_t)f * 9;
        g_comb[p * EMB + f] = w[a] + w[6 + b];
    }
}
__global__ void zero_stats() {
    int t = blockIdx.x * 256 + threadIdx.x;
    if (t < 1800) g_stats[t] = 0.0f;
}
__global__ void init_agg(const float* __restrict__ x, int use_x, const float* __restrict__ eps, int l) {
    int i = blockIdx.x * 256 + threadIdx.x;
    if (i < NN * C75) {
        const float4* h = reinterpret_cast<const float4*>(use_x ? x : g_h);
        float s = 1.0f + eps[l];
        float4 v = h[i];
        v.x *= s; v.y *= s; v.z *= s; v.w *= s;
        reinterpret_cast<float4*>(g_agg)[i] = v;
    }
}
__global__ void edge_scatter(const float* __restrict__ x, int use_x,
                             const int* __restrict__ ei, const int* __restrict__ attr) {
    int idx = blockIdx.x * 256 + threadIdx.x;
    if (idx >= EE * C75) return;
    int e = idx / C75;
    int c = idx - e * C75;
    const float* h = use_x ? x : g_h;
    int src = ei[e];
    int dst = ei[EE + e];
    int2 av = *reinterpret_cast<const int2*>(attr + 2 * e);
    float4 hv = *reinterpret_cast<const float4*>(h + (size_t)src * EMB + 4 * c);
    float4 ev = *reinterpret_cast<const float4*>(g_comb + (av.x * 3 + av.y) * EMB + 4 * c);
    float4 m;
    m.x = fmaxf(hv.x + ev.x, 0.0f);
    m.y = fmaxf(hv.y + ev.y, 0.0f);
    m.z = fmaxf(hv.z + ev.z, 0.0f);
    m.w = fmaxf(hv.w + ev.w, 0.0f);
    float* a = g_agg + (size_t)dst * EMB + 4 * c;
    atomicAdd(a + 0, m.x);
    atomicAdd(a + 1, m.y);
    atomicAdd(a + 2, m.z);
    atomicAdd(a + 3, m.w);
}

// ---------------- split to bf16 hi/lo planes ----------------
// srcsel: 0 = external ptr (weights), 1 = g_agg, 2 = g_z1 (with bn1+relu transform)
// dstsel resolved in DEVICE code (host must never pass __device__ symbol addresses).
__global__ void split_fp32(const float* __restrict__ xsrc, int srcsel, int dstsel,
                           int rows, int K, int Kp) {
    const float* src = (srcsel == 1) ? g_agg : ((srcsel == 2) ? g_z1 : xsrc);
    __nv_bfloat16 *hi, *lo;
    switch (dstsel) {
        case 0:  hi = g_aggH; lo = g_aggL; break;
        case 1:  hi = g_z1aH; lo = g_z1aL; break;
        case 2:  hi = g_w1H;  lo = g_w1L;  break;
        default: hi = g_w2H;  lo = g_w2L;  break;
    }
    const int c8n = Kp >> 3;
    int idx = blockIdx.x * 256 + threadIdx.x;
    if (idx >= rows * c8n) return;
    int r = idx / c8n;
    int c8 = (idx - r * c8n) << 3;
    float v[8];
    const float* p = src + (size_t)r * K + c8;
    if (c8 + 8 <= K) {
        float4 a = *reinterpret_cast<const float4*>(p);
        float4 b = *reinterpret_cast<const float4*>(p + 4);
        v[0] = a.x; v[1] = a.y; v[2] = a.z; v[3] = a.w;
        v[4] = b.x; v[5] = b.y; v[6] = b.z; v[7] = b.w;
    } else {
#pragma unroll
        for (int j = 0; j < 8; j++) v[j] = (c8 + j < K) ? p[j] : 0.f;
    }
    if (srcsel == 2) {
#pragma unroll
        for (int j = 0; j < 8; j++)
            v[j] = (c8 + j < K) ? fmaxf(fmaf(v[j], g_scale1[c8 + j], g_shift1[c8 + j]), 0.f) : 0.f;
    }
    uint4 h4, l4;
    split2(v[0], v[1], h4.x, l4.x);
    split2(v[2], v[3], h4.y, l4.y);
    split2(v[4], v[5], h4.z, l4.z);
    split2(v[6], v[7], h4.w, l4.w);
    *reinterpret_cast<uint4*>(hi + (size_t)r * Kp + c8) = h4;
    *reinterpret_cast<uint4*>(lo + (size_t)r * Kp + c8) = l4;
}

// ---------------- bf16x3 GEMM, 3-stage cp.async pipeline ----------------
// block 128x64, BK=32, 8 warps (4M x 2N), warp tile 32x32
// stage (24576B): AH[8192] AL[8192] BH[4096] BL[4096]; 3 stages in dynamic smem
__global__ __launch_bounds__(256, 2)
void gemm_bf16(int sel, const float* __restrict__ bias, int M, int Nc, int nChunks) {
    extern __shared__ __align__(1024) char sm[];
    const uint32_t smBase = smem_u32(sm);

    const __nv_bfloat16 *Ah, *Al, *Bh, *Bl;
    int ldk;
    float *Cout, *statSum, *statSq;
    if (sel == 0) {
        Ah = g_aggH; Al = g_aggL; Bh = g_w1H; Bl = g_w1L; ldk = KP1;
        Cout = g_z1; statSum = g_stats; statSq = g_stats + 600;
    } else {
        Ah = g_z1aH; Al = g_z1aL; Bh = g_w2H; Bl = g_w2L; ldk = KP2;
        Cout = g_z2; statSum = g_stats + 1200; statSq = g_stats + 1500;
    }

    const int tid = threadIdx.x;
    const int wid = tid >> 5;
    const int lane = tid & 31;
    const int row0 = blockIdx.y * 128;
    const int col0 = blockIdx.x * 64;

    // cp.async mapping: 4 threads per row, 16B (8 bf16) per thread
    const int la_r = tid >> 2;    // 0..63
    const int la_c = tid & 3;     // chunk-of-8 within 32 elements

    float acc[2][4][4];
#pragma unroll
    for (int i = 0; i < 2; i++)
#pragma unroll
        for (int j = 0; j < 4; j++)
#pragma unroll
            for (int r = 0; r < 4; r++) acc[i][j][r] = 0.f;

    const int wm = wid >> 1;
    const int wn = wid & 1;
    const int wr = wm * 32;
    const int wc = wn * 32;

    // ---- stage loader: 6 cp.async x 16B per thread ----
    auto load_stage = [&](int slot, int ch) {
        const int k0 = ch * 32;
        const uint32_t base = smBase + slot * STAGE_BYTES;
#pragma unroll
        for (int p = 0; p < 2; p++) {
            int r = la_r + p * 64;                 // A row 0..127
            uint32_t off = (uint32_t)(r * 64 + ((la_c ^ ((r >> 1) & 3)) << 4));
            bool v = (row0 + r) < M;
            size_t gr = v ? (size_t)(row0 + r) : 0;
            cp16(base + off,        Ah + gr * ldk + k0 + la_c * 8, v);
            cp16(base + 8192 + off, Al + gr * ldk + k0 + la_c * 8, v);
        }
        {
            int r = la_r;                          // B row 0..63
            uint32_t off = (uint32_t)(r * 64 + ((la_c ^ ((r >> 1) & 3)) << 4));
            bool v = (col0 + r) < Nc;
            size_t gc = v ? (size_t)(col0 + r) : 0;
            cp16(base + 16384 + off, Bh + gc * ldk + k0 + la_c * 8, v);
            cp16(base + 20480 + off, Bl + gc * ldk + k0 + la_c * 8, v);
        }
    };

    // prologue: stages 0 and 1 (nChunks >= 2 always: 10 or 19)
    load_stage(0, 0); CP_COMMIT;
    load_stage(1, 1); CP_COMMIT;

    for (int ch = 0; ch < nChunks; ch++) {
        if (ch + 1 < nChunks) { CP_WAIT1; } else { CP_WAIT0; }
        __syncthreads();
        if (ch + 2 < nChunks) {
            load_stage((ch + 2) % NSTAGES, ch + 2);
            CP_COMMIT;
        }

        const uint32_t base = smBase + (ch % NSTAGES) * STAGE_BYTES;
        const uint32_t aHi = base, aLo = base + 8192;
        const uint32_t bHi = base + 16384, bLo = base + 20480;
#pragma unroll
        for (int ks = 0; ks < 2; ks++) {
            const int kb = ks * 32 + ((lane >> 4) << 4);
            uint32_t ahi[2][4], alo[2][4];
#pragma unroll
            for (int i = 0; i < 2; i++) {
                uint32_t off = swz(wr + i * 16 + (lane & 15), kb);
                ldsm4(ahi[i], aHi + off);
                ldsm4(alo[i], aLo + off);
            }
#pragma unroll
            for (int jj = 0; jj < 2; jj++) {
                int rn = wc + jj * 16 + ((lane >> 3) & 1) * 8 + (lane & 7);
                uint32_t off = swz(rn, kb);
                uint32_t bh[4], bl[4];
                ldsm4(bh, bHi + off);
                ldsm4(bl, bLo + off);
#pragma unroll
                for (int i = 0; i < 2; i++) {
                    mma16816(acc[i][2 * jj],     ahi[i], bh[0], bh[2]);
                    mma16816(acc[i][2 * jj + 1], ahi[i], bh[1], bh[3]);
                    mma16816(acc[i][2 * jj],     ahi[i], bl[0], bl[2]);
                    mma16816(acc[i][2 * jj + 1], ahi[i], bl[1], bl[3]);
                    mma16816(acc[i][2 * jj],     alo[i], bh[0], bh[2]);
                    mma16816(acc[i][2 * jj + 1], alo[i], bh[1], bh[3]);
                }
            }
        }
    }
    __syncthreads();   // all compute done before smem reuse below

    // ---- epilogue: bias + store + BN stats ----
    float* sSum = reinterpret_cast<float*>(sm);
    float* sSq  = sSum + 64;
    if (tid < 64) { sSum[tid] = 0.f; sSq[tid] = 0.f; }
    __syncthreads();

    const int g  = lane >> 2;
    const int tg = lane & 3;
    float bv[8];
#pragma unroll
    for (int j = 0; j < 4; j++) {
        int gc = col0 + wc + j * 8 + tg * 2;
        bool cv = gc < Nc;
        bv[2 * j]     = cv ? bias[gc] : 0.f;
        bv[2 * j + 1] = cv ? bias[gc + 1] : 0.f;
    }
    float csum[8], csq[8];
#pragma unroll
    for (int k = 0; k < 8; k++) { csum[k] = 0.f; csq[k] = 0.f; }

#pragma unroll
    for (int i = 0; i < 2; i++) {
        int ra = row0 + wr + i * 16 + g;
        int rb = ra + 8;
#pragma unroll
        for (int j = 0; j < 4; j++) {
            int gc = col0 + wc + j * 8 + tg * 2;
            if (gc < Nc) {
                float o0 = acc[i][j][0] + bv[2 * j];
                float o1 = acc[i][j][1] + bv[2 * j + 1];
                if (ra < M) {
                    *reinterpret_cast<float2*>(Cout + (size_t)ra * Nc + gc) = make_float2(o0, o1);
                    csum[2 * j] += o0; csum[2 * j + 1] += o1;
                    csq[2 * j] += o0 * o0; csq[2 * j + 1] += o1 * o1;
                }
                float o2 = acc[i][j][2] + bv[2 * j];
                float o3 = acc[i][j][3] + bv[2 * j + 1];
                if (rb < M) {
                    *reinterpret_cast<float2*>(Cout + (size_t)rb * Nc + gc) = make_float2(o2, o3);
                    csum[2 * j] += o2; csum[2 * j + 1] += o3;
                    csq[2 * j] += o2 * o2; csq[2 * j + 1] += o3 * o3;
                }
            }
        }
    }
#pragma unroll
    for (int off = 4; off <= 16; off <<= 1) {
#pragma unroll
        for (int k = 0; k < 8; k++) {
            csum[k] += __shfl_xor_sync(0xffffffffu, csum[k], off);
            csq[k]  += __shfl_xor_sync(0xffffffffu, csq[k], off);
        }
    }
    if (lane < 4) {
#pragma unroll
        for (int j = 0; j < 4; j++) {
            int c = wc + j * 8 + lane * 2;
            if (col0 + c < Nc) {
                atomicAdd(&sSum[c], csum[2 * j]);
                atomicAdd(&sSum[c + 1], csum[2 * j + 1]);
                atomicAdd(&sSq[c], csq[2 * j]);
                atomicAdd(&sSq[c + 1], csq[2 * j + 1]);
            }
        }
    }
    __syncthreads();
    if (tid < 64 && col0 + tid < Nc) {
        atomicAdd(statSum + col0 + tid, sSum[tid]);
        atomicAdd(statSq + col0 + tid, sSq[tid]);
    }
}

__global__ void finalize_bn(const float* __restrict__ gamma, const float* __restrict__ beta,
                            int l, int sel) {
    int Ccols = sel ? EMB : EMB2;
    const float* sum = sel ? (g_stats + 1200) : g_stats;
    const float* sq  = sel ? (g_stats + 1500) : (g_stats + 600);
    float* scale = sel ? g_scale2 : g_scale1;
    float* shift = sel ? g_shift2 : g_shift1;
    int j = blockIdx.x * 256 + threadIdx.x;
    if (j < Ccols) {
        float inv = 1.0f / (float)NN;
        float m = sum[j] * inv;
        float v = sq[j] * inv - m * m;
        float sc = gamma[l * Ccols + j] * rsqrtf(v + 1e-5f);
        scale[j] = sc;
        shift[j] = beta[l * Ccols + j] - m * sc;
    }
}

__global__ void apply_out(float* __restrict__ dout, int use_dout, int do_relu) {
    int i = blockIdx.x * 256 + threadIdx.x;
    if (i < NN * C75) {
        int c4 = (i % C75) * 4;
        float4 v = reinterpret_cast<const float4*>(g_z2)[i];
        float4 sc = *reinterpret_cast<const float4*>(g_scale2 + c4);
        float4 sh = *reinterpret_cast<const float4*>(g_shift2 + c4);
        v.x = fmaf(v.x, sc.x, sh.x);
        v.y = fmaf(v.y, sc.y, sh.y);
        v.z = fmaf(v.z, sc.z, sh.z);
        v.w = fmaf(v.w, sc.w, sh.w);
        if (do_relu) {
            v.x = fmaxf(v.x, 0.f);
            v.y = fmaxf(v.y, 0.f);
            v.z = fmaxf(v.z, 0.f);
            v.w = fmaxf(v.w, 0.f);
        }
        float4* o = use_dout ? reinterpret_cast<float4*>(dout) : reinterpret_cast<float4*>(g_h);
        o[i] = v;
    }
}

// ---------------- host ----------------
extern "C" void kernel_launch(void* const* d_in, const int* in_sizes, int n_in,
                              void* d_out, int out_size) {
    const float* x    = (const float*)d_in[0];
    const float* Wb   = (const float*)d_in[1];
    const float* eps  = (const float*)d_in[2];
    const float* W1   = (const float*)d_in[3];
    const float* b1   = (const float*)d_in[4];
    const float* bn1g = (const float*)d_in[5];
    const float* bn1b = (const float*)d_in[6];
    const float* W2   = (const float*)d_in[7];
    const float* b2   = (const float*)d_in[8];
    const float* bng  = (const float*)d_in[9];
    const float* bnb  = (const float*)d_in[10];
    const int*   ei   = (const int*)d_in[11];
    const int*   attr = (const int*)d_in[12];
    float* out = (float*)d_out;

    cudaFuncSetAttribute(gemm_bf16, cudaFuncAttributeMaxDynamicSharedMemorySize, GEMM_SMEM);

    const int gridA = (NN * C75 + 255) / 256;
    const int gridE = (EE * C75 + 255) / 256;
    const int rowT  = (NN + 127) / 128;            // 782
    const int cb1   = (EMB2 + 63) / 64;            // 10
    const int cb2   = (EMB + 63) / 64;             // 5
    const int nch1  = KP1 / 32;                    // 10
    const int nch2  = KP2 / 32;                    // 19
    const int gsA   = (NN * (KP1 / 8) + 255) / 256;
    const int gsZ   = (NN * (KP2 / 8) + 255) / 256;
    const int gsW1  = (EMB2 * (KP1 / 8) + 255) / 256;
    const int gsW2  = (EMB * (KP2 / 8) + 255) / 256;

    for (int l = 0; l < LAY; l++) {
        int use_x = (l == 0) ? 1 : 0;
        build_comb<<<(18 * EMB + 255) / 256, 256>>>(Wb, l);
        zero_stats<<<(1800 + 255) / 256, 256>>>();
        init_agg<<<gridA, 256>>>(x, use_x, eps, l);
        edge_scatter<<<gridE, 256>>>(x, use_x, ei, attr);
        split_fp32<<<gsA, 256>>>(nullptr, 1, 0, NN, EMB, KP1);
        split_fp32<<<gsW1, 256>>>(W1 + (size_t)l * EMB2 * EMB, 0, 2, EMB2, EMB, KP1);
        gemm_bf16<<<dim3(cb1, rowT), 256, GEMM_SMEM>>>(0, b1 + l * EMB2, NN, EMB2, nch1);
        finalize_bn<<<(EMB2 + 255) / 256, 256>>>(bn1g, bn1b, l, 0);
        split_fp32<<<gsZ, 256>>>(nullptr, 2, 1, NN, EMB2, KP2);
        split_fp32<<<gsW2, 256>>>(W2 + (size_t)l * EMB * EMB2, 0, 3, EMB, EMB2, KP2);
        gemm_bf16<<<dim3(cb2, rowT), 256, GEMM_SMEM>>>(1, b2 + l * EMB, NN, EMB, nch2);
        finalize_bn<<<(EMB + 255) / 256, 256>>>(bng, bnb, l, 1);
        apply_out<<<gridA, 256>>>(out, (l == LAY - 1) ? 1 : 0, (l < LAY - 1) ? 1 : 0);
    }
}